// round 8
// baseline (speedup 1.0000x reference)
#include <cuda_runtime.h>

#define DIN   32
#define H     128
#define TSRC  256
#define TGT   64
#define RB    4        // batch rows per block
#define NBLK  128
#define NTHR  256

// Packed weight storage: Wp[k*H + j] = float4( W[(0H+j)K+k], W[(1H+j)K+k], W[(2H+j)K+k], W[(3H+j)K+k] )
// offsets in float4 units inside g_wp
#define OFF_E0X 0                      // DIN*H = 4096
#define OFF_E0H (OFF_E0X + DIN*H)      // H*H = 16384
#define OFF_E1I (OFF_E0H + H*H)
#define OFF_E1H (OFF_E1I + H*H)
#define OFF_D0X (OFF_E1H + H*H)
#define OFF_D0H (OFF_D0X + DIN*H)
#define OFF_D1I (OFF_D0H + H*H)
#define OFF_D1H (OFF_D1I + H*H)
#define WP_TOTAL (OFF_D1H + H*H)

__device__ float4 g_wp[WP_TOTAL];      // ~1.7 MB
__device__ float4 g_bias[4 * H];       // [set: e0,e1,d0,d1][j] = bih+bhh per gate
__device__ float  g_linT[H * DIN];     // linT[j*DIN + k] = lin_W[k*H + j]

// ---------------- packing kernels (run once per launch, cheap) ----------------
__global__ void pack_w(const float* __restrict__ W, int dstOff, int K) {
    int idx = blockIdx.x * blockDim.x + threadIdx.x;
    if (idx >= K * H) return;
    int k = idx / H, j = idx % H;
    g_wp[dstOff + idx] = make_float4(W[(0 * H + j) * K + k],
                                     W[(1 * H + j) * K + k],
                                     W[(2 * H + j) * K + k],
                                     W[(3 * H + j) * K + k]);
}

__global__ void pack_b(const float* __restrict__ bih, const float* __restrict__ bhh, int set) {
    int j = threadIdx.x;  // 128 threads
    g_bias[set * H + j] = make_float4(bih[0 * H + j] + bhh[0 * H + j],
                                      bih[1 * H + j] + bhh[1 * H + j],
                                      bih[2 * H + j] + bhh[2 * H + j],
                                      bih[3 * H + j] + bhh[3 * H + j]);
}

__global__ void pack_lin(const float* __restrict__ W) {
    int idx = blockIdx.x * blockDim.x + threadIdx.x;  // H*DIN
    if (idx >= H * DIN) return;
    int j = idx / DIN, k = idx % DIN;
    g_linT[j * DIN + k] = W[k * H + j];
}

// ---------------- activations (branch-free, MUFU-based) ----------------
__device__ __forceinline__ float sigf(float x) {
    return __fdividef(1.0f, 1.0f + __expf(-x));
}
__device__ __forceinline__ float tnh(float x) {
    return __fdividef(2.0f, 1.0f + __expf(-2.0f * x)) - 1.0f;
}
// gate order from jnp.split: x=i, y=f, z=g, w=o
__device__ __forceinline__ float cellp(float4 a, float& c) {
    float i = sigf(a.x), f = sigf(a.y), g = tnh(a.z), o = sigf(a.w);
    c = f * c + i * g;
    return o * tnh(c);
}

#define FMA8(w, va, vb, Aa, Ab)                                         \
    Aa.x += w.x * va; Aa.y += w.y * va; Aa.z += w.z * va; Aa.w += w.w * va; \
    Ab.x += w.x * vb; Ab.y += w.y * vb; Ab.z += w.z * vb; Ab.w += w.w * vb;

// ---------------- main persistent-sequence kernel ----------------
__global__ void __launch_bounds__(NTHR, 1)
lstm_main(const float* __restrict__ x, const float* __restrict__ linb,
          float* __restrict__ out) {
    __shared__ float h0s[RB][H];
    __shared__ float h1s[RB][H];
    __shared__ float xs[RB][DIN];

    const int tid = threadIdx.x;
    const int j   = tid & (H - 1);
    const int p   = tid >> 7;             // 0/1
    const int ra  = 2 * p, rb = 2 * p + 1;
    const int rbase = blockIdx.x * RB;

    const float4* __restrict__ e0x = g_wp + OFF_E0X;
    const float4* __restrict__ e0h = g_wp + OFF_E0H;
    const float4* __restrict__ e1i = g_wp + OFF_E1I;
    const float4* __restrict__ e1h = g_wp + OFF_E1H;
    const float4* __restrict__ d0x = g_wp + OFF_D0X;
    const float4* __restrict__ d0h = g_wp + OFF_D0H;
    const float4* __restrict__ d1i = g_wp + OFF_D1I;
    const float4* __restrict__ d1h = g_wp + OFF_D1H;

    for (int i2 = tid; i2 < RB * H; i2 += NTHR) {
        ((float*)h0s)[i2] = 0.0f;
        ((float*)h1s)[i2] = 0.0f;
    }
    float c0a = 0.f, c0b = 0.f, c1a = 0.f, c1b = 0.f;

    const float4 b0 = g_bias[0 * H + j];
    const float4 b1 = g_bias[1 * H + j];
    const float4 b2 = g_bias[2 * H + j];
    const float4 b3 = g_bias[3 * H + j];
    const float4 z4 = make_float4(0.f, 0.f, 0.f, 0.f);
    __syncthreads();

    // ================= encoder =================
    for (int t = 0; t < TSRC; t++) {
        if (tid < RB * DIN) {
            int r = tid >> 5, k = tid & 31;
            xs[r][k] = x[(rbase + r) * (TSRC * DIN) + t * DIN + k];
        }
        __syncthreads();

        // ---- layer 0 ----
        float4 Aa = b0, Ab = b0;
        #pragma unroll 8
        for (int k = 0; k < DIN; k++) {
            float4 w = e0x[k * H + j];
            float va = xs[ra][k], vb = xs[rb][k];
            FMA8(w, va, vb, Aa, Ab)
        }
        #pragma unroll 8
        for (int k = 0; k < H; k++) {
            float4 w = e0h[k * H + j];
            float va = h0s[ra][k], vb = h0s[rb][k];
            FMA8(w, va, vb, Aa, Ab)
        }
        float nh0a = cellp(Aa, c0a);
        float nh0b = cellp(Ab, c0b);
        __syncthreads();                 // all old-h0 reads done
        h0s[ra][j] = nh0a;
        h0s[rb][j] = nh0b;
        __syncthreads();

        // ---- layer 1 (input = new h0, recur = old h1); two accumulator pairs for ILP ----
        float4 Ba = b1, Bb = b1, Ca = z4, Cb = z4;
        #pragma unroll 8
        for (int k = 0; k < H; k++) {
            float4 w = e1i[k * H + j];
            float va = h0s[ra][k], vb = h0s[rb][k];
            FMA8(w, va, vb, Ba, Bb)
        }
        #pragma unroll 8
        for (int k = 0; k < H; k++) {
            float4 w = e1h[k * H + j];
            float va = h1s[ra][k], vb = h1s[rb][k];
            FMA8(w, va, vb, Ca, Cb)
        }
        Ba.x += Ca.x; Ba.y += Ca.y; Ba.z += Ca.z; Ba.w += Ca.w;
        Bb.x += Cb.x; Bb.y += Cb.y; Bb.z += Cb.z; Bb.w += Cb.w;
        float nh1a = cellp(Ba, c1a);
        float nh1b = cellp(Bb, c1b);
        __syncthreads();                 // all old-h1 reads done
        h1s[ra][j] = nh1a;
        h1s[rb][j] = nh1b;
        __syncthreads();
    }

    // ================= decoder =================
    if (tid < RB * DIN) {                // dec_in0 = x[:, -1, :]
        int r = tid >> 5, k = tid & 31;
        xs[r][k] = x[(rbase + r) * (TSRC * DIN) + (TSRC - 1) * DIN + k];
    }
    __syncthreads();

    for (int tt = 0; tt < TGT; tt++) {
        // ---- dec layer 0 ----
        float4 Aa = b2, Ab = b2;
        #pragma unroll 8
        for (int k = 0; k < DIN; k++) {
            float4 w = d0x[k * H + j];
            float va = xs[ra][k], vb = xs[rb][k];
            FMA8(w, va, vb, Aa, Ab)
        }
        #pragma unroll 8
        for (int k = 0; k < H; k++) {
            float4 w = d0h[k * H + j];
            float va = h0s[ra][k], vb = h0s[rb][k];
            FMA8(w, va, vb, Aa, Ab)
        }
        float nh0a = cellp(Aa, c0a);
        float nh0b = cellp(Ab, c0b);
        __syncthreads();
        h0s[ra][j] = nh0a;
        h0s[rb][j] = nh0b;
        __syncthreads();

        // ---- dec layer 1 ----
        float4 Ba = b3, Bb = b3, Ca = z4, Cb = z4;
        #pragma unroll 8
        for (int k = 0; k < H; k++) {
            float4 w = d1i[k * H + j];
            float va = h0s[ra][k], vb = h0s[rb][k];
            FMA8(w, va, vb, Ba, Bb)
        }
        #pragma unroll 8
        for (int k = 0; k < H; k++) {
            float4 w = d1h[k * H + j];
            float va = h1s[ra][k], vb = h1s[rb][k];
            FMA8(w, va, vb, Ca, Cb)
        }
        Ba.x += Ca.x; Ba.y += Ca.y; Ba.z += Ca.z; Ba.w += Ca.w;
        Bb.x += Cb.x; Bb.y += Cb.y; Bb.z += Cb.z; Bb.w += Cb.w;
        float nh1a = cellp(Ba, c1a);
        float nh1b = cellp(Bb, c1b);
        __syncthreads();
        h1s[ra][j] = nh1a;
        h1s[rb][j] = nh1b;
        __syncthreads();

        // ---- linear head + feedback: out = h1 @ lin_W.T + lin_b ----
        if (tid < RB * DIN) {
            int r = tid >> 5, k = tid & 31;
            float acc = linb[k];
            #pragma unroll 8
            for (int j2 = 0; j2 < H; j2++)
                acc += h1s[r][j2] * g_linT[j2 * DIN + k];
            xs[r][k] = acc;
            out[(rbase + r) * (TGT * DIN) + tt * DIN + k] = acc;
        }
        __syncthreads();
    }
}

// ---------------- host entry ----------------
extern "C" void kernel_launch(void* const* d_in, const int* in_sizes, int n_in,
                              void* d_out, int out_size) {
    const float* x    = (const float*)d_in[0];
    // d_in[1] = target_len (constant 64, shapes fixed)
    const float* eW0  = (const float*)d_in[2];
    const float* eU0  = (const float*)d_in[3];
    const float* ebi0 = (const float*)d_in[4];
    const float* ebh0 = (const float*)d_in[5];
    const float* eW1  = (const float*)d_in[6];
    const float* eU1  = (const float*)d_in[7];
    const float* ebi1 = (const float*)d_in[8];
    const float* ebh1 = (const float*)d_in[9];
    const float* dW0  = (const float*)d_in[10];
    const float* dU0  = (const float*)d_in[11];
    const float* dbi0 = (const float*)d_in[12];
    const float* dbh0 = (const float*)d_in[13];
    const float* dW1  = (const float*)d_in[14];
    const float* dU1  = (const float*)d_in[15];
    const float* dbi1 = (const float*)d_in[16];
    const float* dbh1 = (const float*)d_in[17];
    const float* linW = (const float*)d_in[18];
    const float* linb = (const float*)d_in[19];

    const int GS = 256;
    pack_w<<<(DIN * H + GS - 1) / GS, GS>>>(eW0, OFF_E0X, DIN);
    pack_w<<<(H * H + GS - 1) / GS, GS>>>(eU0, OFF_E0H, H);
    pack_w<<<(H * H + GS - 1) / GS, GS>>>(eW1, OFF_E1I, H);
    pack_w<<<(H * H + GS - 1) / GS, GS>>>(eU1, OFF_E1H, H);
    pack_w<<<(DIN * H + GS - 1) / GS, GS>>>(dW0, OFF_D0X, DIN);
    pack_w<<<(H * H + GS - 1) / GS, GS>>>(dU0, OFF_D0H, H);
    pack_w<<<(H * H + GS - 1) / GS, GS>>>(dW1, OFF_D1I, H);
    pack_w<<<(H * H + GS - 1) / GS, GS>>>(dU1, OFF_D1H, H);
    pack_b<<<1, H>>>(ebi0, ebh0, 0);
    pack_b<<<1, H>>>(ebi1, ebh1, 1);
    pack_b<<<1, H>>>(dbi0, dbh0, 2);
    pack_b<<<1, H>>>(dbi1, dbh1, 3);
    pack_lin<<<(H * DIN + GS - 1) / GS, GS>>>(linW);

    lstm_main<<<NBLK, NTHR>>>(x, linb, (float*)d_out);
}

// round 12
// speedup vs baseline: 1.1880x; 1.1880x over previous
#include <cuda_runtime.h>

#define DIN   32
#define H     128
#define TSRC  256
#define TGT   64
#define HP    68          // padded row stride of staged-h smem buffer (floats)
#define NTHR  256
#define NBLK  128

typedef unsigned long long ull;

// ---------------- device-global state ----------------
// packed weights: dst[k*128 + j] = float4(i,f,g,o gate weights), rows stacked
// [Wih (KX rows) ; Whh (KH rows)]
__device__ float4 g_wE0[160 * 128];
__device__ float4 g_wE1[256 * 128];
__device__ float4 g_wD0[160 * 128];
__device__ float4 g_wD1[256 * 128];
__device__ float4 g_bias[4 * 128];          // set 0..3 = e0,e1,d0,d1 ; (bih+bhh) per gate
__device__ float  g_h0[2][8 * H * 64];      // [slot][bg][j][row]
__device__ float  g_h1[2][8 * H * 64];
__device__ float  g_fb[8 * DIN * 64];       // [bg][m][row] decoder feedback
__device__ unsigned g_bar[8 * 32];          // per-bg barrier counters (padded)

// ---------------- packing / init kernels ----------------
__global__ void pack_stack(const float* __restrict__ Wx, const float* __restrict__ Wh,
                           float4* __restrict__ dst, int KX, int KH) {
    int idx = blockIdx.x * blockDim.x + threadIdx.x;
    int KT = KX + KH;
    if (idx >= KT * 128) return;
    int k = idx >> 7, j = idx & 127;
    float4 v;
    if (k < KX) {
        v.x = Wx[(0 * H + j) * KX + k];
        v.y = Wx[(1 * H + j) * KX + k];
        v.z = Wx[(2 * H + j) * KX + k];
        v.w = Wx[(3 * H + j) * KX + k];
    } else {
        int kk = k - KX;
        v.x = Wh[(0 * H + j) * KH + kk];
        v.y = Wh[(1 * H + j) * KH + kk];
        v.z = Wh[(2 * H + j) * KH + kk];
        v.w = Wh[(3 * H + j) * KH + kk];
    }
    dst[idx] = v;
}

__global__ void pack_bias(const float* __restrict__ bih, const float* __restrict__ bhh, int set) {
    int j = threadIdx.x;   // 128
    g_bias[set * 128 + j] = make_float4(bih[0 * H + j] + bhh[0 * H + j],
                                        bih[1 * H + j] + bhh[1 * H + j],
                                        bih[2 * H + j] + bhh[2 * H + j],
                                        bih[3 * H + j] + bhh[3 * H + j]);
}

__global__ void zero_bar() {
    g_bar[threadIdx.x] = 0u;
}

// ---------------- packed f32x2 helpers (proven bit-identical to scalar in R8/R10) ----------------
__device__ __forceinline__ void ffma2(ull& d, ull a, ull b) {
    asm("fma.rn.f32x2 %0, %1, %2, %0;" : "+l"(d) : "l"(a), "l"(b));
}
__device__ __forceinline__ ull dup2(float v) {
    ull r; asm("mov.b64 %0, {%1, %1};" : "=l"(r) : "f"(v)); return r;
}
__device__ __forceinline__ ull pk2(float a, float b) {
    ull r; asm("mov.b64 %0, {%1, %2};" : "=l"(r) : "f"(a), "f"(b)); return r;
}
__device__ __forceinline__ float2 up2(ull v) {
    float2 r; asm("mov.b64 {%0, %1}, %2;" : "=f"(r.x), "=f"(r.y) : "l"(v)); return r;
}

// ---------------- activations (identical to R7 PASS: rel_err 5.2e-7) ----------------
__device__ __forceinline__ float sigf(float x) { return __fdividef(1.f, 1.f + __expf(-x)); }
__device__ __forceinline__ float tnh(float x)  { return __fdividef(2.f, 1.f + __expf(-2.f * x)) - 1.f; }
__device__ __forceinline__ float cellf(float2 if_, float2 go_, float& c) {
    float i = sigf(if_.x), f = sigf(if_.y), g = tnh(go_.x), o = sigf(go_.y);
    c = f * c + i * g;
    return o * tnh(c);
}

// ---------------- staging helpers (cross-block data -> L2-only accesses) ----------------
// FIXED R11: stage the FULL 64x32 input tile (2 float4s per thread; R8/R10 staged only half).
__device__ __forceinline__ void stage_x(const float* x, float* hb, int rbase, int t, int tid) {
    int row = tid >> 2, kq = tid & 3;
    #pragma unroll
    for (int half = 0; half < 2; half++) {
        int k0 = (kq + 4 * half) * 4;        // 0,4,..,28 -> covers k=0..31
        float4 v = *(const float4*)(x + (size_t)(rbase + row) * (TSRC * DIN) + t * DIN + k0);
        hb[(k0 + 0) * HP + row] = v.x;
        hb[(k0 + 1) * HP + row] = v.y;
        hb[(k0 + 2) * HP + row] = v.z;
        hb[(k0 + 3) * HP + row] = v.w;
    }
}

__device__ __forceinline__ void stage_h(const float* src, float* hb, int koff, int tid) {
    int j = tid >> 1, half = tid & 1;
    const float* s = src + j * 64 + half * 32;
    float* d = hb + (koff + j) * HP + half * 32;
    #pragma unroll
    for (int it = 0; it < 8; it++) {
        float4 v = __ldcg((const float4*)(s + it * 4));   // L2-only: no L1 staleness possible
        *(float4*)(d + it * 4) = v;
    }
}

__device__ __forceinline__ void stage_fb(const float* src, float* hb, int tid) {
    #pragma unroll
    for (int s2 = 0; s2 < 2; s2++) {
        int idx4 = tid * 2 + s2;
        int m = idx4 >> 4, off = (idx4 & 15) * 4;
        float4 v = __ldcg((const float4*)(src + m * 64 + off));
        *(float4*)(hb + m * HP + off) = v;
    }
}

// ---------------- per-bg barrier (16 blocks), release/acquire ----------------
__device__ __forceinline__ void bg_barrier(int bg, unsigned target) {
    __syncthreads();
    if (threadIdx.x == 0) {
        unsigned* ctr = &g_bar[bg * 32];
        asm volatile("red.release.gpu.global.add.u32 [%0], %1;"
                     :: "l"(ctr), "r"(1u) : "memory");
        unsigned v;
        do {
            asm volatile("ld.acquire.gpu.global.u32 %0, [%1];"
                         : "=r"(v) : "l"(ctr) : "memory");
            if (v >= target) break;
            __nanosleep(32);
        } while (true);
    }
    __syncthreads();
}

// ---------------- GEMV + cell (one LSTM layer slice), packed f32x2 ----------------
template<int K>
__device__ __forceinline__ void do_layer(const float4* __restrict__ sw,
                                         const float* __restrict__ hb,
                                         float4 b, int jj, int q,
                                         float& cr0, float& cr1,
                                         float* gdst, int jglob) {
    ull aIF0 = pk2(b.x, b.y), aGO0 = pk2(b.z, b.w);
    ull aIF1 = aIF0, aGO1 = aGO0;
    #pragma unroll 8
    for (int k = 0; k < K; k++) {
        ulonglong2 w = *(const ulonglong2*)(sw + k * 8 + jj);       // LDS.128 broadcast
        float2 h2 = *(const float2*)(hb + k * HP + 2 * q);          // LDS.64 row pair
        ull d0 = dup2(h2.x), d1 = dup2(h2.y);
        ffma2(aIF0, w.x, d0); ffma2(aGO0, w.y, d0);
        ffma2(aIF1, w.x, d1); ffma2(aGO1, w.y, d1);
    }
    float h0 = cellf(up2(aIF0), up2(aGO0), cr0);
    float h1 = cellf(up2(aIF1), up2(aGO1), cr1);
    __stcg((float2*)(gdst + jglob * 64 + 2 * q), make_float2(h0, h1));
}

// ---------------- main persistent kernel ----------------
__global__ void __launch_bounds__(NTHR, 1)
lstm_main(const float* __restrict__ x, const float* __restrict__ linW,
          const float* __restrict__ linb, float* __restrict__ out) {
    extern __shared__ float smf[];
    float4* swE0 = (float4*)smf;             // 1280 f4
    float4* swE1 = swE0 + 1280;              // 2048 f4
    float4* swD0 = swE1 + 2048;              // 1280 f4
    float4* swD1 = swD0 + 1280;              // 2048 f4
    float4* sb   = swD1 + 2048;              // 32 f4
    float*  slin = (float*)(sb + 32);        // 256
    float*  slnb = slin + 256;               // 2 (+2 pad)
    float*  hbuf = slnb + 4;                 // 288*HP floats

    const int tid = threadIdx.x;
    const int bg = blockIdx.x >> 4, cg = blockIdx.x & 15;
    const int rbase = bg * 64;
    const int q = tid & 31, jj = tid >> 5;
    const int jglob = cg * 8 + jj;
    const int col0 = cg * 8;

    // load weight slices / bias / lin into smem (once)
    for (int i = tid; i < 1280; i += NTHR) swE0[i] = g_wE0[(i >> 3) * 128 + col0 + (i & 7)];
    for (int i = tid; i < 2048; i += NTHR) swE1[i] = g_wE1[(i >> 3) * 128 + col0 + (i & 7)];
    for (int i = tid; i < 1280; i += NTHR) swD0[i] = g_wD0[(i >> 3) * 128 + col0 + (i & 7)];
    for (int i = tid; i < 2048; i += NTHR) swD1[i] = g_wD1[(i >> 3) * 128 + col0 + (i & 7)];
    if (tid < 32) sb[tid] = g_bias[(tid >> 3) * 128 + col0 + (tid & 7)];
    for (int i = tid; i < 256; i += NTHR) slin[i] = linW[(2 * cg + (i >> 7)) * 128 + (i & 127)];
    if (tid < 2) slnb[tid] = linb[2 * cg + tid];
    for (int i = tid; i < 288 * HP; i += NTHR) hbuf[i] = 0.f;
    __syncthreads();

    const float4 be0 = sb[0 * 8 + jj], be1 = sb[1 * 8 + jj];
    const float4 bd0 = sb[2 * 8 + jj], bd1 = sb[3 * 8 + jj];

    float c00 = 0.f, c01 = 0.f, c10 = 0.f, c11 = 0.f;
    unsigned nbar = 0;

    // ============ encoder: phase p computes layer0(p) and layer1(p-1) ============
    for (int p = 0; p <= TSRC; p++) {
        if (p < TSRC) stage_x(x, hbuf, rbase, p, tid);
        if (p >= 1) stage_h(g_h0[(p - 1) & 1] + bg * 8192, hbuf, 32, tid);   // h0(p-1)
        if (p >= 2) stage_h(g_h1[p & 1] + bg * 8192, hbuf, 160, tid);        // h1(p-2)
        __syncthreads();
        if (p < TSRC)
            do_layer<160>(swE0, hbuf, be0, jj, q, c00, c01, g_h0[p & 1] + bg * 8192, jglob);
        if (p >= 1)
            do_layer<256>(swE1, hbuf + 32 * HP, be1, jj, q, c10, c11,
                          g_h1[(p - 1) & 1] + bg * 8192, jglob);
        nbar++; bg_barrier(bg, nbar * 16);
    }

    // ============ decoder: 3 phases per step ============
    for (int tt = 0; tt < TGT; tt++) {
        // ---- phase A: layer0 ----
        if (tt == 0) stage_x(x, hbuf, rbase, TSRC - 1, tid);        // dec_in0 = x[:, -1, :]
        else         stage_fb(g_fb + bg * 2048, hbuf, tid);
        stage_h(g_h0[(tt + 1) & 1] + bg * 8192, hbuf, 32, tid);     // h0 prev
        __syncthreads();
        do_layer<160>(swD0, hbuf, bd0, jj, q, c00, c01, g_h0[tt & 1] + bg * 8192, jglob);
        nbar++; bg_barrier(bg, nbar * 16);

        // ---- phase B: layer1 ----
        stage_h(g_h0[tt & 1] + bg * 8192, hbuf, 32, tid);           // h0(tt) fresh
        stage_h(g_h1[(tt + 1) & 1] + bg * 8192, hbuf, 160, tid);    // h1 prev
        __syncthreads();
        do_layer<256>(swD1, hbuf + 32 * HP, bd1, jj, q, c10, c11,
                      g_h1[tt & 1] + bg * 8192, jglob);
        nbar++; bg_barrier(bg, nbar * 16);

        // ---- phase C: linear head + feedback ----
        stage_h(g_h1[tt & 1] + bg * 8192, hbuf, 0, tid);            // full h1(tt)
        __syncthreads();
        if (tid < 128) {
            int row = tid & 63, mi = tid >> 6;
            float a0 = slnb[mi], a1 = 0.f, a2 = 0.f, a3 = 0.f;
            #pragma unroll 8
            for (int j = 0; j < 128; j += 4) {
                a0 += hbuf[(j + 0) * HP + row] * slin[mi * 128 + j + 0];
                a1 += hbuf[(j + 1) * HP + row] * slin[mi * 128 + j + 1];
                a2 += hbuf[(j + 2) * HP + row] * slin[mi * 128 + j + 2];
                a3 += hbuf[(j + 3) * HP + row] * slin[mi * 128 + j + 3];
            }
            float acc = (a0 + a1) + (a2 + a3);
            int m = 2 * cg + mi;
            out[(size_t)(rbase + row) * (TGT * DIN) + tt * DIN + m] = acc;
            __stcg(&g_fb[bg * 2048 + m * 64 + row], acc);
        }
        nbar++; bg_barrier(bg, nbar * 16);
    }
}

// ---------------- host entry ----------------
extern "C" void kernel_launch(void* const* d_in, const int* in_sizes, int n_in,
                              void* d_out, int out_size) {
    const float* x    = (const float*)d_in[0];
    const float* eW0  = (const float*)d_in[2];
    const float* eU0  = (const float*)d_in[3];
    const float* ebi0 = (const float*)d_in[4];
    const float* ebh0 = (const float*)d_in[5];
    const float* eW1  = (const float*)d_in[6];
    const float* eU1  = (const float*)d_in[7];
    const float* ebi1 = (const float*)d_in[8];
    const float* ebh1 = (const float*)d_in[9];
    const float* dW0  = (const float*)d_in[10];
    const float* dU0  = (const float*)d_in[11];
    const float* dbi0 = (const float*)d_in[12];
    const float* dbh0 = (const float*)d_in[13];
    const float* dW1  = (const float*)d_in[14];
    const float* dU1  = (const float*)d_in[15];
    const float* dbi1 = (const float*)d_in[16];
    const float* dbh1 = (const float*)d_in[17];
    const float* linW = (const float*)d_in[18];
    const float* linb = (const float*)d_in[19];

    static const int SMEM_BYTES = (1280 + 2048 + 1280 + 2048 + 32) * 16 + (256 + 4) * 4
                                  + 288 * HP * 4;   // 186384 B
    cudaFuncSetAttribute(lstm_main, cudaFuncAttributeMaxDynamicSharedMemorySize, SMEM_BYTES);

    float4 *wE0, *wE1, *wD0, *wD1;
    cudaGetSymbolAddress((void**)&wE0, g_wE0);
    cudaGetSymbolAddress((void**)&wE1, g_wE1);
    cudaGetSymbolAddress((void**)&wD0, g_wD0);
    cudaGetSymbolAddress((void**)&wD1, g_wD1);

    pack_stack<<<(160 * 128 + 255) / 256, 256>>>(eW0, eU0, wE0, DIN, H);
    pack_stack<<<(256 * 128 + 255) / 256, 256>>>(eW1, eU1, wE1, H, H);
    pack_stack<<<(160 * 128 + 255) / 256, 256>>>(dW0, dU0, wD0, DIN, H);
    pack_stack<<<(256 * 128 + 255) / 256, 256>>>(dW1, dU1, wD1, H, H);
    pack_bias<<<1, 128>>>(ebi0, ebh0, 0);
    pack_bias<<<1, 128>>>(ebi1, ebh1, 1);
    pack_bias<<<1, 128>>>(dbi0, dbh0, 2);
    pack_bias<<<1, 128>>>(dbi1, dbh1, 3);
    zero_bar<<<1, 256>>>();

    lstm_main<<<NBLK, NTHR, SMEM_BYTES>>>(x, linW, linb, (float*)d_out);
}

// round 13
// speedup vs baseline: 1.2005x; 1.0105x over previous
#include <cuda_runtime.h>

#define DIN   32
#define H     128
#define TSRC  256
#define TGT   64
#define HP    68          // padded row stride of staged-h smem buffer (floats)
#define NTHR  256
#define NBLK  128

typedef unsigned long long ull;

// ---------------- device-global state ----------------
// packed weights: dst[k*128 + j] = float4(i,f,g,o gate weights), rows stacked
// [Wih (KX rows) ; Whh (KH rows)]
__device__ float4 g_wE0[160 * 128];
__device__ float4 g_wE1[256 * 128];
__device__ float4 g_wD0[160 * 128];
__device__ float4 g_wD1[256 * 128];
__device__ float4 g_bias[4 * 128];          // set 0..3 = e0,e1,d0,d1 ; (bih+bhh) per gate
__device__ float  g_h0[2][8 * H * 64];      // [slot][bg][j][row]
__device__ float  g_h1[2][8 * H * 64];
__device__ float  g_fb2[2][8 * DIN * 64];   // [slot][bg][m][row] decoder head accumulator
__device__ unsigned g_bar[8 * 32];          // per-bg barrier counters (padded)

// ---------------- fused prep kernel (pack weights + bias, zero barriers) ----------------
// flat index ranges: [0,20480) E0 | [20480,53248) E1 | [53248,73728) D0 |
// [73728,106496) D1 | [106496,107008) bias | [107008,107264) bar-zero
__device__ __forceinline__ void pack_one(const float* Wx, const float* Wh,
                                         float4* dst, int KX, int KH, int idx) {
    int k = idx >> 7, j = idx & 127;
    float4 v;
    if (k < KX) {
        v.x = Wx[(0 * H + j) * KX + k];
        v.y = Wx[(1 * H + j) * KX + k];
        v.z = Wx[(2 * H + j) * KX + k];
        v.w = Wx[(3 * H + j) * KX + k];
    } else {
        int kk = k - KX;
        v.x = Wh[(0 * H + j) * KH + kk];
        v.y = Wh[(1 * H + j) * KH + kk];
        v.z = Wh[(2 * H + j) * KH + kk];
        v.w = Wh[(3 * H + j) * KH + kk];
    }
    dst[idx] = v;
}

__global__ void prep(const float* eW0, const float* eU0, const float* eW1, const float* eU1,
                     const float* dW0, const float* dU0, const float* dW1, const float* dU1,
                     const float* ebi0, const float* ebh0, const float* ebi1, const float* ebh1,
                     const float* dbi0, const float* dbh0, const float* dbi1, const float* dbh1) {
    int i = blockIdx.x * blockDim.x + threadIdx.x;
    if (i < 20480)            pack_one(eW0, eU0, g_wE0, DIN, H, i);
    else if (i < 53248)       pack_one(eW1, eU1, g_wE1, H,   H, i - 20480);
    else if (i < 73728)       pack_one(dW0, dU0, g_wD0, DIN, H, i - 53248);
    else if (i < 106496)      pack_one(dW1, dU1, g_wD1, H,   H, i - 73728);
    else if (i < 107008) {
        int r = i - 106496, set = r >> 7, j = r & 127;
        const float* bi = (set == 0) ? ebi0 : (set == 1) ? ebi1 : (set == 2) ? dbi0 : dbi1;
        const float* bh = (set == 0) ? ebh0 : (set == 1) ? ebh1 : (set == 2) ? dbh0 : dbh1;
        g_bias[set * 128 + j] = make_float4(bi[0 * H + j] + bh[0 * H + j],
                                            bi[1 * H + j] + bh[1 * H + j],
                                            bi[2 * H + j] + bh[2 * H + j],
                                            bi[3 * H + j] + bh[3 * H + j]);
    } else if (i < 107264) {
        g_bar[i - 107008] = 0u;
    }
}

// ---------------- packed f32x2 helpers ----------------
__device__ __forceinline__ void ffma2(ull& d, ull a, ull b) {
    asm("fma.rn.f32x2 %0, %1, %2, %0;" : "+l"(d) : "l"(a), "l"(b));
}
__device__ __forceinline__ ull dup2(float v) {
    ull r; asm("mov.b64 %0, {%1, %1};" : "=l"(r) : "f"(v)); return r;
}
__device__ __forceinline__ ull pk2(float a, float b) {
    ull r; asm("mov.b64 %0, {%1, %2};" : "=l"(r) : "f"(a), "f"(b)); return r;
}
__device__ __forceinline__ float2 up2(ull v) {
    float2 r; asm("mov.b64 {%0, %1}, %2;" : "=f"(r.x), "=f"(r.y) : "l"(v)); return r;
}

// ---------------- activations ----------------
__device__ __forceinline__ float sigf(float x) { return __fdividef(1.f, 1.f + __expf(-x)); }
__device__ __forceinline__ float tnh(float x)  { return __fdividef(2.f, 1.f + __expf(-2.f * x)) - 1.f; }
__device__ __forceinline__ float cellf(float2 if_, float2 go_, float& c) {
    float i = sigf(if_.x), f = sigf(if_.y), g = tnh(go_.x), o = sigf(go_.y);
    c = f * c + i * g;
    return o * tnh(c);
}

// ---------------- staging helpers (cross-block data -> L2-only accesses) ----------------
__device__ __forceinline__ void stage_x(const float* x, float* hb, int rbase, int t, int tid) {
    int row = tid >> 2, kq = tid & 3;
    #pragma unroll
    for (int half = 0; half < 2; half++) {
        int k0 = (kq + 4 * half) * 4;        // covers k=0..31
        float4 v = *(const float4*)(x + (size_t)(rbase + row) * (TSRC * DIN) + t * DIN + k0);
        hb[(k0 + 0) * HP + row] = v.x;
        hb[(k0 + 1) * HP + row] = v.y;
        hb[(k0 + 2) * HP + row] = v.z;
        hb[(k0 + 3) * HP + row] = v.w;
    }
}

__device__ __forceinline__ void stage_h(const float* src, float* hb, int koff, int tid) {
    int j = tid >> 1, half = tid & 1;
    const float* s = src + j * 64 + half * 32;
    float* d = hb + (koff + j) * HP + half * 32;
    #pragma unroll
    for (int it = 0; it < 8; it++) {
        float4 v = __ldcg((const float4*)(s + it * 4));
        *(float4*)(d + it * 4) = v;
    }
}

__device__ __forceinline__ void stage_fb(const float* src, float* hb, int tid) {
    #pragma unroll
    for (int s2 = 0; s2 < 2; s2++) {
        int idx4 = tid * 2 + s2;
        int m = idx4 >> 4, off = (idx4 & 15) * 4;
        float4 v = __ldcg((const float4*)(src + m * 64 + off));
        *(float4*)(hb + m * HP + off) = v;
    }
}

// ---------------- per-bg barrier (16 blocks), release/acquire ----------------
__device__ __forceinline__ void bg_barrier(int bg, unsigned target) {
    __syncthreads();
    if (threadIdx.x == 0) {
        unsigned* ctr = &g_bar[bg * 32];
        asm volatile("red.release.gpu.global.add.u32 [%0], %1;"
                     :: "l"(ctr), "r"(1u) : "memory");
        unsigned v;
        do {
            asm volatile("ld.acquire.gpu.global.u32 %0, [%1];"
                         : "=r"(v) : "l"(ctr) : "memory");
            if (v >= target) break;
            __nanosleep(32);
        } while (true);
    }
    __syncthreads();
}

// ---------------- GEMV + cell (one LSTM layer slice), packed f32x2 ----------------
template<int K>
__device__ __forceinline__ float2 do_layer(const float4* __restrict__ sw,
                                           const float* __restrict__ hb,
                                           float4 b, int jj, int q,
                                           float& cr0, float& cr1) {
    ull aIF0 = pk2(b.x, b.y), aGO0 = pk2(b.z, b.w);
    ull aIF1 = aIF0, aGO1 = aGO0;
    #pragma unroll 8
    for (int k = 0; k < K; k++) {
        ulonglong2 w = *(const ulonglong2*)(sw + k * 8 + jj);       // LDS.128 broadcast
        float2 h2 = *(const float2*)(hb + k * HP + 2 * q);          // LDS.64 row pair
        ull d0 = dup2(h2.x), d1 = dup2(h2.y);
        ffma2(aIF0, w.x, d0); ffma2(aGO0, w.y, d0);
        ffma2(aIF1, w.x, d1); ffma2(aGO1, w.y, d1);
    }
    float h0 = cellf(up2(aIF0), up2(aGO0), cr0);
    float h1 = cellf(up2(aIF1), up2(aGO1), cr1);
    return make_float2(h0, h1);
}

// ---------------- main persistent kernel ----------------
__global__ void __launch_bounds__(NTHR, 1)
lstm_main(const float* __restrict__ x, const float* __restrict__ linW,
          const float* __restrict__ linb, float* __restrict__ out) {
    extern __shared__ float smf[];
    float4* swE0 = (float4*)smf;             // 1280 f4
    float4* swE1 = swE0 + 1280;              // 2048 f4
    float4* swD0 = swE1 + 2048;              // 1280 f4
    float4* swD1 = swD0 + 1280;              // 2048 f4
    float4* sb   = swD1 + 2048;              // 32 f4
    float*  slin2 = (float*)(sb + 32);       // [32 m][8 local j] = 256
    float*  slnb32 = slin2 + 256;            // 32
    float*  h1loc  = slnb32 + 32;            // [8 jj][68] = 544
    float*  hbuf   = h1loc + 544;            // 288*HP floats

    const int tid = threadIdx.x;
    const int bg = blockIdx.x >> 4, cg = blockIdx.x & 15;
    const int rbase = bg * 64;
    const int q = tid & 31, jj = tid >> 5;
    const int jglob = cg * 8 + jj;
    const int col0 = cg * 8;

    // load weight slices / bias / lin into smem (once)
    for (int i = tid; i < 1280; i += NTHR) swE0[i] = g_wE0[(i >> 3) * 128 + col0 + (i & 7)];
    for (int i = tid; i < 2048; i += NTHR) swE1[i] = g_wE1[(i >> 3) * 128 + col0 + (i & 7)];
    for (int i = tid; i < 1280; i += NTHR) swD0[i] = g_wD0[(i >> 3) * 128 + col0 + (i & 7)];
    for (int i = tid; i < 2048; i += NTHR) swD1[i] = g_wD1[(i >> 3) * 128 + col0 + (i & 7)];
    if (tid < 32) sb[tid] = g_bias[(tid >> 3) * 128 + col0 + (tid & 7)];
    if (tid < 256) slin2[tid] = linW[(tid >> 3) * H + col0 + (tid & 7)];   // [m][jj]
    if (tid < 32) slnb32[tid] = linb[tid];
    for (int i = tid; i < 288 * HP; i += NTHR) hbuf[i] = 0.f;
    __syncthreads();

    const float4 be0 = sb[0 * 8 + jj], be1 = sb[1 * 8 + jj];
    const float4 bd0 = sb[2 * 8 + jj], bd1 = sb[3 * 8 + jj];

    float c00 = 0.f, c01 = 0.f, c10 = 0.f, c11 = 0.f;
    unsigned nbar = 0;

    // ============ encoder: phase p computes layer0(p) and layer1(p-1) ============
    for (int p = 0; p <= TSRC; p++) {
        if (p < TSRC) stage_x(x, hbuf, rbase, p, tid);
        if (p >= 1) stage_h(g_h0[(p - 1) & 1] + bg * 8192, hbuf, 32, tid);   // h0(p-1)
        if (p >= 2) stage_h(g_h1[p & 1] + bg * 8192, hbuf, 160, tid);        // h1(p-2)
        __syncthreads();
        if (p < TSRC) {
            float2 hp = do_layer<160>(swE0, hbuf, be0, jj, q, c00, c01);
            __stcg((float2*)(g_h0[p & 1] + bg * 8192 + jglob * 64 + 2 * q), hp);
        }
        if (p >= 1) {
            float2 hp = do_layer<256>(swE1, hbuf + 32 * HP, be1, jj, q, c10, c11);
            __stcg((float2*)(g_h1[(p - 1) & 1] + bg * 8192 + jglob * 64 + 2 * q), hp);
        }
        nbar++; bg_barrier(bg, nbar * 16);
    }

    // ============ decoder: 2 phases per step ============
    const int orow = tid & 63, om0 = tid >> 6;     // out/init mapping: 4 m-groups x 64 rows
    for (int tt = 0; tt < TGT; tt++) {
        // ---- phase A: layer0 (+ fb init, + out write for tt-1) ----
        if (tt == 0) {
            stage_x(x, hbuf, rbase, TSRC - 1, tid);          // dec_in0 = x[:, -1, :]
        } else {
            const float* fbsrc = g_fb2[(tt + 1) & 1] + bg * 2048;   // slot (tt-1)&1
            stage_fb(fbsrc, hbuf, tid);
            if (cg == 0) {                                    // write out[:, tt-1, :]
                #pragma unroll
                for (int u = 0; u < 8; u++) {
                    int m = om0 * 8 + u;
                    float v = __ldcg(fbsrc + m * 64 + orow);
                    out[(size_t)(rbase + orow) * (TGT * DIN) + (tt - 1) * DIN + m] = v;
                }
            }
        }
        // init fb accumulator slot tt&1 to linb (consumed by phase B atomics)
        if (cg == 0) {
            #pragma unroll
            for (int u = 0; u < 8; u++) {
                int m = om0 * 8 + u;
                __stcg(&g_fb2[tt & 1][bg * 2048 + m * 64 + orow], slnb32[m]);
            }
        }
        stage_h(g_h0[(tt + 1) & 1] + bg * 8192, hbuf, 32, tid);     // h0 prev
        __syncthreads();
        {
            float2 hp = do_layer<160>(swD0, hbuf, bd0, jj, q, c00, c01);
            __stcg((float2*)(g_h0[tt & 1] + bg * 8192 + jglob * 64 + 2 * q), hp);
        }
        nbar++; bg_barrier(bg, nbar * 16);

        // ---- phase B: layer1 + local head partial (atomic accumulate) ----
        stage_h(g_h0[tt & 1] + bg * 8192, hbuf, 32, tid);           // h0(tt) fresh
        stage_h(g_h1[(tt + 1) & 1] + bg * 8192, hbuf, 160, tid);    // h1 prev
        __syncthreads();
        {
            float2 hp = do_layer<256>(swD1, hbuf + 32 * HP, bd1, jj, q, c10, c11);
            __stcg((float2*)(g_h1[tt & 1] + bg * 8192 + jglob * 64 + 2 * q), hp);
            h1loc[jj * 68 + 2 * q] = hp.x;
            h1loc[jj * 68 + 2 * q + 1] = hp.y;
        }
        __syncthreads();
        #pragma unroll
        for (int u = 0; u < 8; u++) {
            int m = om0 * 8 + u;
            float acc = 0.f;
            #pragma unroll
            for (int j2 = 0; j2 < 8; j2++)
                acc += h1loc[j2 * 68 + orow] * slin2[m * 8 + j2];
            atomicAdd(&g_fb2[tt & 1][bg * 2048 + m * 64 + orow], acc);
        }
        nbar++; bg_barrier(bg, nbar * 16);
    }

    // ---- epilogue: write out[:, TGT-1, :] ----
    if (cg == 0) {
        const float* fbsrc = g_fb2[(TGT - 1) & 1] + bg * 2048;
        #pragma unroll
        for (int u = 0; u < 8; u++) {
            int m = om0 * 8 + u;
            float v = __ldcg(fbsrc + m * 64 + orow);
            out[(size_t)(rbase + orow) * (TGT * DIN) + (TGT - 1) * DIN + m] = v;
        }
    }
}

// ---------------- host entry ----------------
extern "C" void kernel_launch(void* const* d_in, const int* in_sizes, int n_in,
                              void* d_out, int out_size) {
    const float* x    = (const float*)d_in[0];
    const float* eW0  = (const float*)d_in[2];
    const float* eU0  = (const float*)d_in[3];
    const float* ebi0 = (const float*)d_in[4];
    const float* ebh0 = (const float*)d_in[5];
    const float* eW1  = (const float*)d_in[6];
    const float* eU1  = (const float*)d_in[7];
    const float* ebi1 = (const float*)d_in[8];
    const float* ebh1 = (const float*)d_in[9];
    const float* dW0  = (const float*)d_in[10];
    const float* dU0  = (const float*)d_in[11];
    const float* dbi0 = (const float*)d_in[12];
    const float* dbh0 = (const float*)d_in[13];
    const float* dW1  = (const float*)d_in[14];
    const float* dU1  = (const float*)d_in[15];
    const float* dbi1 = (const float*)d_in[16];
    const float* dbh1 = (const float*)d_in[17];
    const float* linW = (const float*)d_in[18];
    const float* linb = (const float*)d_in[19];

    static const int SMEM_BYTES = (1280 + 2048 + 1280 + 2048 + 32) * 16
                                  + (256 + 32 + 544) * 4 + 288 * HP * 4;   // ~188.7 KB
    cudaFuncSetAttribute(lstm_main, cudaFuncAttributeMaxDynamicSharedMemorySize, SMEM_BYTES);

    prep<<<(107264 + 255) / 256, 256>>>(eW0, eU0, eW1, eU1, dW0, dU0, dW1, dU1,
                                        ebi0, ebh0, ebi1, ebh1, dbi0, dbh0, dbi1, dbh1);
    lstm_main<<<NBLK, NTHR, SMEM_BYTES>>>(x, linW, linb, (float*)d_out);
}

// round 14
// speedup vs baseline: 1.2108x; 1.0086x over previous
#include <cuda_runtime.h>

#define DIN   32
#define H     128
#define TSRC  256
#define TGT   64
#define HP    68          // padded row stride of staged-h smem buffer (floats)
#define NTHR  256
#define NBLK  128

typedef unsigned long long ull;

// ---------------- device-global state ----------------
// packed weights: dst[k*128 + j] = float4(i,f,g,o gate weights), rows stacked
// [Wih (KX rows) ; Whh (KH rows)]
__device__ float4 g_wE0[160 * 128];
__device__ float4 g_wE1[256 * 128];
__device__ float4 g_wD0[160 * 128];
__device__ float4 g_wD1[256 * 128];
__device__ float4 g_bias[4 * 128];          // set 0..3 = e0,e1,d0,d1 ; (bih+bhh) per gate
__device__ float  g_h0[2][8 * H * 64];      // [slot][bg][j][row]
__device__ float  g_h1[2][8 * H * 64];
__device__ float  g_fb2[2][8 * DIN * 64];   // [slot][bg][m][row] decoder head accumulator
__device__ unsigned g_bar[8 * 32];          // per-bg barrier counters (padded)

// ---------------- fused prep kernel (pack weights + bias, zero barriers) ----------------
__device__ __forceinline__ void pack_one(const float* Wx, const float* Wh,
                                         float4* dst, int KX, int KH, int idx) {
    int k = idx >> 7, j = idx & 127;
    float4 v;
    if (k < KX) {
        v.x = Wx[(0 * H + j) * KX + k];
        v.y = Wx[(1 * H + j) * KX + k];
        v.z = Wx[(2 * H + j) * KX + k];
        v.w = Wx[(3 * H + j) * KX + k];
    } else {
        int kk = k - KX;
        v.x = Wh[(0 * H + j) * KH + kk];
        v.y = Wh[(1 * H + j) * KH + kk];
        v.z = Wh[(2 * H + j) * KH + kk];
        v.w = Wh[(3 * H + j) * KH + kk];
    }
    dst[idx] = v;
}

__global__ void prep(const float* eW0, const float* eU0, const float* eW1, const float* eU1,
                     const float* dW0, const float* dU0, const float* dW1, const float* dU1,
                     const float* ebi0, const float* ebh0, const float* ebi1, const float* ebh1,
                     const float* dbi0, const float* dbh0, const float* dbi1, const float* dbh1) {
    int i = blockIdx.x * blockDim.x + threadIdx.x;
    if (i < 20480)            pack_one(eW0, eU0, g_wE0, DIN, H, i);
    else if (i < 53248)       pack_one(eW1, eU1, g_wE1, H,   H, i - 20480);
    else if (i < 73728)       pack_one(dW0, dU0, g_wD0, DIN, H, i - 53248);
    else if (i < 106496)      pack_one(dW1, dU1, g_wD1, H,   H, i - 73728);
    else if (i < 107008) {
        int r = i - 106496, set = r >> 7, j = r & 127;
        const float* bi = (set == 0) ? ebi0 : (set == 1) ? ebi1 : (set == 2) ? dbi0 : dbi1;
        const float* bh = (set == 0) ? ebh0 : (set == 1) ? ebh1 : (set == 2) ? dbh0 : dbh1;
        g_bias[set * 128 + j] = make_float4(bi[0 * H + j] + bh[0 * H + j],
                                            bi[1 * H + j] + bh[1 * H + j],
                                            bi[2 * H + j] + bh[2 * H + j],
                                            bi[3 * H + j] + bh[3 * H + j]);
    } else if (i < 107264) {
        g_bar[i - 107008] = 0u;
    }
}

// ---------------- packed f32x2 helpers ----------------
__device__ __forceinline__ void ffma2(ull& d, ull a, ull b) {
    asm("fma.rn.f32x2 %0, %1, %2, %0;" : "+l"(d) : "l"(a), "l"(b));
}
__device__ __forceinline__ ull dup2(float v) {
    ull r; asm("mov.b64 %0, {%1, %1};" : "=l"(r) : "f"(v)); return r;
}
__device__ __forceinline__ ull pk2(float a, float b) {
    ull r; asm("mov.b64 %0, {%1, %2};" : "=l"(r) : "f"(a), "f"(b)); return r;
}
__device__ __forceinline__ float2 up2(ull v) {
    float2 r; asm("mov.b64 {%0, %1}, %2;" : "=f"(r.x), "=f"(r.y) : "l"(v)); return r;
}

// ---------------- activations ----------------
__device__ __forceinline__ float sigf(float x) { return __fdividef(1.f, 1.f + __expf(-x)); }
__device__ __forceinline__ float tnh(float x)  { return __fdividef(2.f, 1.f + __expf(-2.f * x)) - 1.f; }
__device__ __forceinline__ float cellf(float2 if_, float2 go_, float& c) {
    float i = sigf(if_.x), f = sigf(if_.y), g = tnh(go_.x), o = sigf(go_.y);
    c = f * c + i * g;
    return o * tnh(c);
}

// ---------------- staging helpers (cross-block data -> L2-only accesses) ----------------
__device__ __forceinline__ void stage_x(const float* x, float* hb, int rbase, int t, int tid) {
    int row = tid >> 2, kq = tid & 3;
    #pragma unroll
    for (int half = 0; half < 2; half++) {
        int k0 = (kq + 4 * half) * 4;        // covers k=0..31
        float4 v = *(const float4*)(x + (size_t)(rbase + row) * (TSRC * DIN) + t * DIN + k0);
        hb[(k0 + 0) * HP + row] = v.x;
        hb[(k0 + 1) * HP + row] = v.y;
        hb[(k0 + 2) * HP + row] = v.z;
        hb[(k0 + 3) * HP + row] = v.w;
    }
}

__device__ __forceinline__ void stage_h(const float* src, float* hb, int koff, int tid) {
    int j = tid >> 1, half = tid & 1;
    const float* s = src + j * 64 + half * 32;
    float* d = hb + (koff + j) * HP + half * 32;
    #pragma unroll
    for (int it = 0; it < 8; it++) {
        float4 v = __ldcg((const float4*)(s + it * 4));
        *(float4*)(d + it * 4) = v;
    }
}

__device__ __forceinline__ void stage_fb(const float* src, float* hb, int tid) {
    #pragma unroll
    for (int s2 = 0; s2 < 2; s2++) {
        int idx4 = tid * 2 + s2;
        int m = idx4 >> 4, off = (idx4 & 15) * 4;
        float4 v = __ldcg((const float4*)(src + m * 64 + off));
        *(float4*)(hb + m * HP + off) = v;
    }
}

// ---------------- per-bg barrier (16 blocks), release/acquire ----------------
__device__ __forceinline__ void bg_barrier(int bg, unsigned target) {
    __syncthreads();
    if (threadIdx.x == 0) {
        unsigned* ctr = &g_bar[bg * 32];
        asm volatile("red.release.gpu.global.add.u32 [%0], %1;"
                     :: "l"(ctr), "r"(1u) : "memory");
        unsigned v;
        do {
            asm volatile("ld.acquire.gpu.global.u32 %0, [%1];"
                         : "=r"(v) : "l"(ctr) : "memory");
            if (v >= target) break;
            __nanosleep(32);
        } while (true);
    }
    __syncthreads();
}

// ---------------- GEMV + cell (one LSTM layer slice), packed f32x2 ----------------
// R13->R14: warp owns 32 rows x 2 cols. cl = local column (0..7), rowoff = row
// offset within 64 (even). Lanes 16-31 duplicate lanes 0-15's h addresses ->
// h LDS.64 dedups to 1 wavefront; w LDS.128 has 2 distinct addrs -> 1 wavefront.
template<int K>
__device__ __forceinline__ float2 do_layer(const float4* __restrict__ sw,
                                           const float* __restrict__ hb,
                                           float4 b, int cl, int rowoff,
                                           float& cr0, float& cr1) {
    ull aIF0 = pk2(b.x, b.y), aGO0 = pk2(b.z, b.w);
    ull aIF1 = aIF0, aGO1 = aGO0;
    #pragma unroll 8
    for (int k = 0; k < K; k++) {
        ulonglong2 w = *(const ulonglong2*)(sw + k * 8 + cl);       // 2 distinct -> 1 wf
        float2 h2 = *(const float2*)(hb + k * HP + rowoff);         // 16 distinct -> 1 wf
        ull d0 = dup2(h2.x), d1 = dup2(h2.y);
        ffma2(aIF0, w.x, d0); ffma2(aGO0, w.y, d0);
        ffma2(aIF1, w.x, d1); ffma2(aGO1, w.y, d1);
    }
    float h0 = cellf(up2(aIF0), up2(aGO0), cr0);
    float h1 = cellf(up2(aIF1), up2(aGO1), cr1);
    return make_float2(h0, h1);
}

// ---------------- main persistent kernel ----------------
__global__ void __launch_bounds__(NTHR, 1)
lstm_main(const float* __restrict__ x, const float* __restrict__ linW,
          const float* __restrict__ linb, float* __restrict__ out) {
    extern __shared__ float smf[];
    float4* swE0 = (float4*)smf;             // 1280 f4
    float4* swE1 = swE0 + 1280;              // 2048 f4
    float4* swD0 = swE1 + 2048;              // 1280 f4
    float4* swD1 = swD0 + 1280;              // 2048 f4
    float4* sb   = swD1 + 2048;              // 32 f4
    float*  slin2 = (float*)(sb + 32);       // [32 m][8 local j] = 256
    float*  slnb32 = slin2 + 256;            // 32
    float*  h1loc  = slnb32 + 32;            // [8 cl][68] = 544
    float*  hbuf   = h1loc + 544;            // 288*HP floats

    const int tid = threadIdx.x;
    const int bg = blockIdx.x >> 4, cg = blockIdx.x & 15;
    const int rbase = bg * 64;
    const int q = tid & 31, wrp = tid >> 5;
    const int rh = wrp & 1;                       // row half (0/1)
    const int cp = wrp >> 1;                      // col pair (0..3)
    const int cl = 2 * cp + (q >> 4);             // local column 0..7
    const int rowoff = 32 * rh + 2 * (q & 15);    // even row offset 0..62
    const int jglob = cg * 8 + cl;
    const int col0 = cg * 8;

    // load weight slices / bias / lin into smem (once)
    for (int i = tid; i < 1280; i += NTHR) swE0[i] = g_wE0[(i >> 3) * 128 + col0 + (i & 7)];
    for (int i = tid; i < 2048; i += NTHR) swE1[i] = g_wE1[(i >> 3) * 128 + col0 + (i & 7)];
    for (int i = tid; i < 1280; i += NTHR) swD0[i] = g_wD0[(i >> 3) * 128 + col0 + (i & 7)];
    for (int i = tid; i < 2048; i += NTHR) swD1[i] = g_wD1[(i >> 3) * 128 + col0 + (i & 7)];
    if (tid < 32) sb[tid] = g_bias[(tid >> 3) * 128 + col0 + (tid & 7)];
    if (tid < 256) slin2[tid] = linW[(tid >> 3) * H + col0 + (tid & 7)];   // [m][cl]
    if (tid < 32) slnb32[tid] = linb[tid];
    for (int i = tid; i < 288 * HP; i += NTHR) hbuf[i] = 0.f;
    __syncthreads();

    const float4 be0 = sb[0 * 8 + cl], be1 = sb[1 * 8 + cl];
    const float4 bd0 = sb[2 * 8 + cl], bd1 = sb[3 * 8 + cl];

    float c00 = 0.f, c01 = 0.f, c10 = 0.f, c11 = 0.f;
    unsigned nbar = 0;

    // ============ encoder: phase p computes layer0(p) and layer1(p-1) ============
    for (int p = 0; p <= TSRC; p++) {
        if (p < TSRC) stage_x(x, hbuf, rbase, p, tid);
        if (p >= 1) stage_h(g_h0[(p - 1) & 1] + bg * 8192, hbuf, 32, tid);   // h0(p-1)
        if (p >= 2) stage_h(g_h1[p & 1] + bg * 8192, hbuf, 160, tid);        // h1(p-2)
        __syncthreads();
        if (p < TSRC) {
            float2 hp = do_layer<160>(swE0, hbuf, be0, cl, rowoff, c00, c01);
            __stcg((float2*)(g_h0[p & 1] + bg * 8192 + jglob * 64 + rowoff), hp);
        }
        if (p >= 1) {
            float2 hp = do_layer<256>(swE1, hbuf + 32 * HP, be1, cl, rowoff, c10, c11);
            __stcg((float2*)(g_h1[(p - 1) & 1] + bg * 8192 + jglob * 64 + rowoff), hp);
        }
        nbar++; bg_barrier(bg, nbar * 16);
    }

    // ============ decoder: 2 phases per step ============
    const int orow = tid & 63, om0 = tid >> 6;     // out/init mapping: 4 m-groups x 64 rows
    for (int tt = 0; tt < TGT; tt++) {
        // ---- phase A: layer0 (+ fb init, + out write for tt-1) ----
        if (tt == 0) {
            stage_x(x, hbuf, rbase, TSRC - 1, tid);          // dec_in0 = x[:, -1, :]
        } else {
            const float* fbsrc = g_fb2[(tt + 1) & 1] + bg * 2048;   // slot (tt-1)&1
            stage_fb(fbsrc, hbuf, tid);
            if (cg == 0) {                                    // write out[:, tt-1, :]
                #pragma unroll
                for (int u = 0; u < 8; u++) {
                    int m = om0 * 8 + u;
                    float v = __ldcg(fbsrc + m * 64 + orow);
                    out[(size_t)(rbase + orow) * (TGT * DIN) + (tt - 1) * DIN + m] = v;
                }
            }
        }
        // init fb accumulator slot tt&1 to linb (consumed by phase B atomics)
        if (cg == 0) {
            #pragma unroll
            for (int u = 0; u < 8; u++) {
                int m = om0 * 8 + u;
                __stcg(&g_fb2[tt & 1][bg * 2048 + m * 64 + orow], slnb32[m]);
            }
        }
        stage_h(g_h0[(tt + 1) & 1] + bg * 8192, hbuf, 32, tid);     // h0 prev
        __syncthreads();
        {
            float2 hp = do_layer<160>(swD0, hbuf, bd0, cl, rowoff, c00, c01);
            __stcg((float2*)(g_h0[tt & 1] + bg * 8192 + jglob * 64 + rowoff), hp);
        }
        nbar++; bg_barrier(bg, nbar * 16);

        // ---- phase B: layer1 + local head partial (atomic accumulate) ----
        stage_h(g_h0[tt & 1] + bg * 8192, hbuf, 32, tid);           // h0(tt) fresh
        stage_h(g_h1[(tt + 1) & 1] + bg * 8192, hbuf, 160, tid);    // h1 prev
        __syncthreads();
        {
            float2 hp = do_layer<256>(swD1, hbuf + 32 * HP, bd1, cl, rowoff, c10, c11);
            __stcg((float2*)(g_h1[tt & 1] + bg * 8192 + jglob * 64 + rowoff), hp);
            h1loc[cl * 68 + rowoff] = hp.x;
            h1loc[cl * 68 + rowoff + 1] = hp.y;
        }
        __syncthreads();
        #pragma unroll
        for (int u = 0; u < 8; u++) {
            int m = om0 * 8 + u;
            float acc = 0.f;
            #pragma unroll
            for (int j2 = 0; j2 < 8; j2++)
                acc += h1loc[j2 * 68 + orow] * slin2[m * 8 + j2];
            atomicAdd(&g_fb2[tt & 1][bg * 2048 + m * 64 + orow], acc);
        }
        nbar++; bg_barrier(bg, nbar * 16);
    }

    // ---- epilogue: write out[:, TGT-1, :] ----
    if (cg == 0) {
        const float* fbsrc = g_fb2[(TGT - 1) & 1] + bg * 2048;
        #pragma unroll
        for (int u = 0; u < 8; u++) {
            int m = om0 * 8 + u;
            float v = __ldcg(fbsrc + m * 64 + orow);
            out[(size_t)(rbase + orow) * (TGT * DIN) + (TGT - 1) * DIN + m] = v;
        }
    }
}

// ---------------- host entry ----------------
extern "C" void kernel_launch(void* const* d_in, const int* in_sizes, int n_in,
                              void* d_out, int out_size) {
    const float* x    = (const float*)d_in[0];
    const float* eW0  = (const float*)d_in[2];
    const float* eU0  = (const float*)d_in[3];
    const float* ebi0 = (const float*)d_in[4];
    const float* ebh0 = (const float*)d_in[5];
    const float* eW1  = (const float*)d_in[6];
    const float* eU1  = (const float*)d_in[7];
    const float* ebi1 = (const float*)d_in[8];
    const float* ebh1 = (const float*)d_in[9];
    const float* dW0  = (const float*)d_in[10];
    const float* dU0  = (const float*)d_in[11];
    const float* dbi0 = (const float*)d_in[12];
    const float* dbh0 = (const float*)d_in[13];
    const float* dW1  = (const float*)d_in[14];
    const float* dU1  = (const float*)d_in[15];
    const float* dbi1 = (const float*)d_in[16];
    const float* dbh1 = (const float*)d_in[17];
    const float* linW = (const float*)d_in[18];
    const float* linb = (const float*)d_in[19];

    static const int SMEM_BYTES = (1280 + 2048 + 1280 + 2048 + 32) * 16
                                  + (256 + 32 + 544) * 4 + 288 * HP * 4;   // ~188.7 KB
    cudaFuncSetAttribute(lstm_main, cudaFuncAttributeMaxDynamicSharedMemorySize, SMEM_BYTES);

    prep<<<(107264 + 255) / 256, 256>>>(eW0, eU0, eW1, eU1, dW0, dU0, dW1, dU1,
                                        ebi0, ebh0, ebi1, ebh1, dbi0, dbh0, dbi1, dbh1);
    lstm_main<<<NBLK, NTHR, SMEM_BYTES>>>(x, linW, linb, (float*)d_out);
}

// round 15
// speedup vs baseline: 1.2676x; 1.0470x over previous
#include <cuda_runtime.h>

#define DIN   32
#define H     128
#define TSRC  256
#define TGT   64
#define HP    68          // padded row stride of staged-h smem buffer (floats)
#define NTHR  512
#define NBLK  128

typedef unsigned long long ull;

// ---------------- device-global state ----------------
__device__ float4 g_wE0[160 * 128];
__device__ float4 g_wE1[256 * 128];
__device__ float4 g_wD0[160 * 128];
__device__ float4 g_wD1[256 * 128];
__device__ float4 g_bias[4 * 128];          // set 0..3 = e0,e1,d0,d1 ; (bih+bhh) per gate
__device__ float  g_h0[2][8 * H * 64];      // [slot][bg][j][row]
__device__ float  g_h1[2][8 * H * 64];
__device__ float  g_fb2[2][8 * DIN * 64];   // [slot][bg][m][row] decoder head accumulator
__device__ unsigned g_bar[8 * 32];          // per-bg barrier counters (padded)

// ---------------- fused prep kernel ----------------
__device__ __forceinline__ void pack_one(const float* Wx, const float* Wh,
                                         float4* dst, int KX, int KH, int idx) {
    int k = idx >> 7, j = idx & 127;
    float4 v;
    if (k < KX) {
        v.x = Wx[(0 * H + j) * KX + k];
        v.y = Wx[(1 * H + j) * KX + k];
        v.z = Wx[(2 * H + j) * KX + k];
        v.w = Wx[(3 * H + j) * KX + k];
    } else {
        int kk = k - KX;
        v.x = Wh[(0 * H + j) * KH + kk];
        v.y = Wh[(1 * H + j) * KH + kk];
        v.z = Wh[(2 * H + j) * KH + kk];
        v.w = Wh[(3 * H + j) * KH + kk];
    }
    dst[idx] = v;
}

__global__ void prep(const float* eW0, const float* eU0, const float* eW1, const float* eU1,
                     const float* dW0, const float* dU0, const float* dW1, const float* dU1,
                     const float* ebi0, const float* ebh0, const float* ebi1, const float* ebh1,
                     const float* dbi0, const float* dbh0, const float* dbi1, const float* dbh1) {
    int i = blockIdx.x * blockDim.x + threadIdx.x;
    if (i < 20480)            pack_one(eW0, eU0, g_wE0, DIN, H, i);
    else if (i < 53248)       pack_one(eW1, eU1, g_wE1, H,   H, i - 20480);
    else if (i < 73728)       pack_one(dW0, dU0, g_wD0, DIN, H, i - 53248);
    else if (i < 106496)      pack_one(dW1, dU1, g_wD1, H,   H, i - 73728);
    else if (i < 107008) {
        int r = i - 106496, set = r >> 7, j = r & 127;
        const float* bi = (set == 0) ? ebi0 : (set == 1) ? ebi1 : (set == 2) ? dbi0 : dbi1;
        const float* bh = (set == 0) ? ebh0 : (set == 1) ? ebh1 : (set == 2) ? dbh0 : dbh1;
        g_bias[set * 128 + j] = make_float4(bi[0 * H + j] + bh[0 * H + j],
                                            bi[1 * H + j] + bh[1 * H + j],
                                            bi[2 * H + j] + bh[2 * H + j],
                                            bi[3 * H + j] + bh[3 * H + j]);
    } else if (i < 107264) {
        g_bar[i - 107008] = 0u;
    }
}

// ---------------- packed f32x2 helpers ----------------
__device__ __forceinline__ void ffma2(ull& d, ull a, ull b) {
    asm("fma.rn.f32x2 %0, %1, %2, %0;" : "+l"(d) : "l"(a), "l"(b));
}
__device__ __forceinline__ ull dup2(float v) {
    ull r; asm("mov.b64 %0, {%1, %1};" : "=l"(r) : "f"(v)); return r;
}

// ---------------- activations ----------------
__device__ __forceinline__ float sigf(float x) { return __fdividef(1.f, 1.f + __expf(-x)); }
__device__ __forceinline__ float tnh(float x)  { return __fdividef(2.f, 1.f + __expf(-2.f * x)) - 1.f; }
__device__ __forceinline__ float cellf(float2 if_, float2 go_, float& c) {
    float i = sigf(if_.x), f = sigf(if_.y), g = tnh(go_.x), o = sigf(go_.y);
    c = f * c + i * g;
    return o * tnh(c);
}

// ---------------- staging helpers (tid-guarded for 512 threads) ----------------
__device__ __forceinline__ void stage_x(const float* x, float* hb, int rbase, int t, int tid) {
    if (tid >= 256) return;
    int row = tid >> 2, kq = tid & 3;
    #pragma unroll
    for (int half = 0; half < 2; half++) {
        int k0 = (kq + 4 * half) * 4;
        float4 v = *(const float4*)(x + (size_t)(rbase + row) * (TSRC * DIN) + t * DIN + k0);
        hb[(k0 + 0) * HP + row] = v.x;
        hb[(k0 + 1) * HP + row] = v.y;
        hb[(k0 + 2) * HP + row] = v.z;
        hb[(k0 + 3) * HP + row] = v.w;
    }
}

__device__ __forceinline__ void stage_h(const float* src, float* hb, int koff, int tid) {
    int j = tid >> 2, q4 = tid & 3;        // 512 threads: 128 j x 4 quarters
    const float* s = src + j * 64 + q4 * 16;
    float* d = hb + (koff + j) * HP + q4 * 16;
    #pragma unroll
    for (int it = 0; it < 4; it++) {
        float4 v = __ldcg((const float4*)(s + it * 4));
        *(float4*)(d + it * 4) = v;
    }
}

__device__ __forceinline__ void stage_fb(const float* src, float* hb, int tid) {
    if (tid >= 256) return;
    #pragma unroll
    for (int s2 = 0; s2 < 2; s2++) {
        int idx4 = tid * 2 + s2;
        int m = idx4 >> 4, off = (idx4 & 15) * 4;
        float4 v = __ldcg((const float4*)(src + m * 64 + off));
        *(float4*)(hb + m * HP + off) = v;
    }
}

// ---------------- per-bg barrier (16 blocks), release/acquire ----------------
__device__ __forceinline__ void bg_barrier(int bg, unsigned target) {
    __syncthreads();
    if (threadIdx.x == 0) {
        unsigned* ctr = &g_bar[bg * 32];
        asm volatile("red.release.gpu.global.add.u32 [%0], %1;"
                     :: "l"(ctr), "r"(1u) : "memory");
        unsigned v;
        do {
            asm volatile("ld.acquire.gpu.global.u32 %0, [%1];"
                         : "=r"(v) : "l"(ctr) : "memory");
            if (v >= target) break;
            __nanosleep(32);
        } while (true);
    }
    __syncthreads();
}

// ---------------- k-sliced accumulate: thread = 2 rows x 2 cols, 4 k-slices ----------------
// acc layout a[c*4 + r*2 + {0:IF,1:GO}], dumped to scratch (64B/thread).
template<int K>
__device__ __forceinline__ void do_accum(const float4* __restrict__ sw,
                                         const float* __restrict__ hb,
                                         int slice, int rowoff, int cp, ull* myscr) {
    ull a0 = 0, a1 = 0, a2 = 0, a3 = 0, a4 = 0, a5 = 0, a6 = 0, a7 = 0;
    const int k0 = slice * (K / 4);
    #pragma unroll 8
    for (int kk = 0; kk < K / 4; kk++) {
        int k = k0 + kk;
        ulonglong2 w0 = *(const ulonglong2*)(sw + k * 8 + 2 * cp);      // col 2cp: (IF)(GO)
        ulonglong2 w1 = *(const ulonglong2*)(sw + k * 8 + 2 * cp + 1);  // col 2cp+1
        float2 h2 = *(const float2*)(hb + k * HP + rowoff);
        ull d0 = dup2(h2.x), d1 = dup2(h2.y);
        ffma2(a0, w0.x, d0); ffma2(a1, w0.y, d0);
        ffma2(a2, w0.x, d1); ffma2(a3, w0.y, d1);
        ffma2(a4, w1.x, d0); ffma2(a5, w1.y, d0);
        ffma2(a6, w1.x, d1); ffma2(a7, w1.y, d1);
    }
    myscr[0] = a0; myscr[1] = a1; myscr[2] = a2; myscr[3] = a3;
    myscr[4] = a4; myscr[5] = a5; myscr[6] = a6; myscr[7] = a7;
}

// ---------------- reduce 4 slabs + bias + cell + store (owner threads tid<128) ----------------
__device__ __forceinline__ void finalize_cell(const float2* __restrict__ scrF2,
                                              const float4* __restrict__ sb_set,
                                              int rp, int cp, float* cs,
                                              float* gdst, int colbase, float* h1loc) {
    const int base_w = (rp >> 4) + 2 * (cp >> 1);
    const int lane_of = (rp & 15) + 16 * (cp & 1);
    float2 V[8];
    #pragma unroll
    for (int i = 0; i < 8; i++) V[i] = make_float2(0.f, 0.f);
    #pragma unroll
    for (int s = 0; s < 4; s++) {
        const float2* p = scrF2 + (size_t)(32 * (4 * s + base_w) + lane_of) * 8;
        #pragma unroll
        for (int i = 0; i < 8; i++) { float2 u = p[i]; V[i].x += u.x; V[i].y += u.y; }
    }
    #pragma unroll
    for (int c = 0; c < 2; c++) {
        float4 b = sb_set[2 * cp + c];
        float2 IF0 = make_float2(V[c * 4 + 0].x + b.x, V[c * 4 + 0].y + b.y);
        float2 GO0 = make_float2(V[c * 4 + 1].x + b.z, V[c * 4 + 1].y + b.w);
        float h0v = cellf(IF0, GO0, cs[c * 2 + 0]);
        float2 IF1 = make_float2(V[c * 4 + 2].x + b.x, V[c * 4 + 2].y + b.y);
        float2 GO1 = make_float2(V[c * 4 + 3].x + b.z, V[c * 4 + 3].y + b.w);
        float h1v = cellf(IF1, GO1, cs[c * 2 + 1]);
        int j = colbase + 2 * cp + c;
        __stcg((float2*)(gdst + j * 64 + 2 * rp), make_float2(h0v, h1v));
        if (h1loc) {
            h1loc[(2 * cp + c) * 68 + 2 * rp] = h0v;
            h1loc[(2 * cp + c) * 68 + 2 * rp + 1] = h1v;
        }
    }
}

// ---------------- main persistent kernel ----------------
__global__ void __launch_bounds__(NTHR, 1)
lstm_main(const float* __restrict__ x, const float* __restrict__ linW,
          const float* __restrict__ linb, float* __restrict__ out) {
    extern __shared__ float smf[];
    float4* swE0 = (float4*)smf;             // 1280 f4
    float4* swE1 = swE0 + 1280;              // 2048 f4
    float4* swD0 = swE1 + 2048;              // 1280 f4
    float4* swD1 = swD0 + 1280;              // 2048 f4
    float4* sb   = swD1 + 2048;              // 32 f4
    float*  slin2 = (float*)(sb + 32);       // [32 m][8 local j]
    float*  slnb32 = slin2 + 256;            // 32
    float*  h1loc  = slnb32 + 32;            // [8 cl][68] = 544
    float*  hbuf   = h1loc + 544;            // 288*HP floats
    ull*    scrU   = (ull*)(hbuf + 288 * HP);        // 512 threads x 8 ull = 32KB
    const float2* scrF2 = (const float2*)scrU;

    const int tid = threadIdx.x;
    const int bg = blockIdx.x >> 4, cg = blockIdx.x & 15;
    const int rbase = bg * 64;
    const int lane = tid & 31, w = tid >> 5;
    const int slice = w >> 2;
    const int rp = 16 * (w & 1) + (lane & 15);      // rowpair 0..31 (rows 2rp, 2rp+1)
    const int cp = 2 * ((w >> 1) & 1) + (lane >> 4); // colpair 0..3 (cols 2cp, 2cp+1)
    const int rowoff = 2 * rp;
    const int col0 = cg * 8;
    ull* myscr = scrU + (size_t)tid * 8;

    // load weight slices / bias / lin into smem (once)
    for (int i = tid; i < 1280; i += NTHR) swE0[i] = g_wE0[(i >> 3) * 128 + col0 + (i & 7)];
    for (int i = tid; i < 2048; i += NTHR) swE1[i] = g_wE1[(i >> 3) * 128 + col0 + (i & 7)];
    for (int i = tid; i < 1280; i += NTHR) swD0[i] = g_wD0[(i >> 3) * 128 + col0 + (i & 7)];
    for (int i = tid; i < 2048; i += NTHR) swD1[i] = g_wD1[(i >> 3) * 128 + col0 + (i & 7)];
    if (tid < 32) sb[tid] = g_bias[(tid >> 3) * 128 + col0 + (tid & 7)];
    if (tid < 256) slin2[tid] = linW[(tid >> 3) * H + col0 + (tid & 7)];   // [m][cl]
    if (tid < 32) slnb32[tid] = linb[tid];
    for (int i = tid; i < 288 * HP; i += NTHR) hbuf[i] = 0.f;
    __syncthreads();

    float cs0[4] = {0.f, 0.f, 0.f, 0.f};   // layer-0 cell state: [c][r], owners tid<128
    float cs1[4] = {0.f, 0.f, 0.f, 0.f};   // layer-1 cell state
    unsigned nbar = 0;

    // ============ encoder: phase p computes layer0(p) and layer1(p-1) ============
    for (int p = 0; p <= TSRC; p++) {
        if (p < TSRC) stage_x(x, hbuf, rbase, p, tid);
        if (p >= 1) stage_h(g_h0[(p - 1) & 1] + bg * 8192, hbuf, 32, tid);   // h0(p-1)
        if (p >= 2) stage_h(g_h1[p & 1] + bg * 8192, hbuf, 160, tid);        // h1(p-2)
        __syncthreads();
        if (p < TSRC) {
            do_accum<160>(swE0, hbuf, slice, rowoff, cp, myscr);
            __syncthreads();
            if (tid < 128)
                finalize_cell(scrF2, sb + 0 * 8, rp, cp, cs0,
                              g_h0[p & 1] + bg * 8192, col0, nullptr);
            __syncthreads();
        }
        if (p >= 1) {
            do_accum<256>(swE1, hbuf + 32 * HP, slice, rowoff, cp, myscr);
            __syncthreads();
            if (tid < 128)
                finalize_cell(scrF2, sb + 1 * 8, rp, cp, cs1,
                              g_h1[(p - 1) & 1] + bg * 8192, col0, nullptr);
        }
        nbar++; bg_barrier(bg, nbar * 16);
    }

    // ============ decoder: 2 phases per step ============
    const int orow = tid & 63, om0 = (tid >> 6) & 3;
    for (int tt = 0; tt < TGT; tt++) {
        // ---- phase A: layer0 (+ fb init, + out write for tt-1) ----
        if (tt == 0) {
            stage_x(x, hbuf, rbase, TSRC - 1, tid);          // dec_in0 = x[:, -1, :]
        } else {
            const float* fbsrc = g_fb2[(tt + 1) & 1] + bg * 2048;   // slot (tt-1)&1
            stage_fb(fbsrc, hbuf, tid);
            if (cg == 0 && tid < 256) {
                #pragma unroll
                for (int u = 0; u < 8; u++) {
                    int m = om0 * 8 + u;
                    float v = __ldcg(fbsrc + m * 64 + orow);
                    out[(size_t)(rbase + orow) * (TGT * DIN) + (tt - 1) * DIN + m] = v;
                }
            }
        }
        if (cg == 0 && tid < 256) {
            #pragma unroll
            for (int u = 0; u < 8; u++) {
                int m = om0 * 8 + u;
                __stcg(&g_fb2[tt & 1][bg * 2048 + m * 64 + orow], slnb32[m]);
            }
        }
        stage_h(g_h0[(tt + 1) & 1] + bg * 8192, hbuf, 32, tid);     // h0 prev
        __syncthreads();
        do_accum<160>(swD0, hbuf, slice, rowoff, cp, myscr);
        __syncthreads();
        if (tid < 128)
            finalize_cell(scrF2, sb + 2 * 8, rp, cp, cs0,
                          g_h0[tt & 1] + bg * 8192, col0, nullptr);
        nbar++; bg_barrier(bg, nbar * 16);

        // ---- phase B: layer1 + head partial (atomic accumulate) ----
        stage_h(g_h0[tt & 1] + bg * 8192, hbuf, 32, tid);           // h0(tt) fresh
        stage_h(g_h1[(tt + 1) & 1] + bg * 8192, hbuf, 160, tid);    // h1 prev
        __syncthreads();
        do_accum<256>(swD1, hbuf + 32 * HP, slice, rowoff, cp, myscr);
        __syncthreads();
        if (tid < 128)
            finalize_cell(scrF2, sb + 3 * 8, rp, cp, cs1,
                          g_h1[tt & 1] + bg * 8192, col0, h1loc);
        __syncthreads();
        if (tid < 256) {
            #pragma unroll
            for (int u = 0; u < 8; u++) {
                int m = om0 * 8 + u;
                float acc = 0.f;
                #pragma unroll
                for (int j2 = 0; j2 < 8; j2++)
                    acc += h1loc[j2 * 68 + orow] * slin2[m * 8 + j2];
                atomicAdd(&g_fb2[tt & 1][bg * 2048 + m * 64 + orow], acc);
            }
        }
        nbar++; bg_barrier(bg, nbar * 16);
    }

    // ---- epilogue: write out[:, TGT-1, :] ----
    if (cg == 0 && tid < 256) {
        const float* fbsrc = g_fb2[(TGT - 1) & 1] + bg * 2048;
        #pragma unroll
        for (int u = 0; u < 8; u++) {
            int m = om0 * 8 + u;
            float v = __ldcg(fbsrc + m * 64 + orow);
            out[(size_t)(rbase + orow) * (TGT * DIN) + (TGT - 1) * DIN + m] = v;
        }
    }
}

// ---------------- host entry ----------------
extern "C" void kernel_launch(void* const* d_in, const int* in_sizes, int n_in,
                              void* d_out, int out_size) {
    const float* x    = (const float*)d_in[0];
    const float* eW0  = (const float*)d_in[2];
    const float* eU0  = (const float*)d_in[3];
    const float* ebi0 = (const float*)d_in[4];
    const float* ebh0 = (const float*)d_in[5];
    const float* eW1  = (const float*)d_in[6];
    const float* eU1  = (const float*)d_in[7];
    const float* ebi1 = (const float*)d_in[8];
    const float* ebh1 = (const float*)d_in[9];
    const float* dW0  = (const float*)d_in[10];
    const float* dU0  = (const float*)d_in[11];
    const float* dbi0 = (const float*)d_in[12];
    const float* dbh0 = (const float*)d_in[13];
    const float* dW1  = (const float*)d_in[14];
    const float* dU1  = (const float*)d_in[15];
    const float* dbi1 = (const float*)d_in[16];
    const float* dbh1 = (const float*)d_in[17];
    const float* linW = (const float*)d_in[18];
    const float* linb = (const float*)d_in[19];

    static const int SMEM_BYTES = (1280 + 2048 + 1280 + 2048 + 32) * 16
                                  + (256 + 32 + 544) * 4 + 288 * HP * 4
                                  + NTHR * 8 * 8;          // 221440 B
    cudaFuncSetAttribute(lstm_main, cudaFuncAttributeMaxDynamicSharedMemorySize, SMEM_BYTES);

    prep<<<(107264 + 255) / 256, 256>>>(eW0, eU0, eW1, eU1, dW0, dU0, dW1, dU1,
                                        ebi0, ebh0, ebi1, ebh1, dbi0, dbh0, dbi1, dbh1);
    lstm_main<<<NBLK, NTHR, SMEM_BYTES>>>(x, linW, linb, (float*)d_out);
}